// round 6
// baseline (speedup 1.0000x reference)
#include <cuda_runtime.h>
#include <cstdint>

#define NV 100000
#define ME 50000
#define D  128
#define WMED (1.0f / 13.0f)

// ---------------- scratch (device globals; no runtime allocation) ----------------
__device__ float g_Y[(size_t)NV * D];   // Y (pre-scaled linear output)
__device__ float g_deg[NV];             // extra degree (actual deg = 1 + g_deg); memset 0
__device__ int   g_pair[ME];

// ---------------- helpers ----------------
__device__ __forceinline__ float4 f4add(float4 a, float4 b) {
    return make_float4(a.x + b.x, a.y + b.y, a.z + b.z, a.w + b.w);
}
__device__ __forceinline__ float4 f4scale(float4 a, float s) {
    return make_float4(a.x * s, a.y * s, a.z * s, a.w * s);
}
__device__ __forceinline__ void red_add_v4(float* p, float4 v) {
    asm volatile("red.global.add.v4.f32 [%0], {%1,%2,%3,%4};"
                 :: "l"(p), "f"(v.x), "f"(v.y), "f"(v.z), "f"(v.w) : "memory");
}
__device__ __forceinline__ float warp_sum(float v) {
#pragma unroll
    for (int o = 16; o > 0; o >>= 1) v += __shfl_xor_sync(0xffffffffu, v, o);
    return v;
}
__device__ __forceinline__ float rsqrt_ref(float dg) {
    float rs = rsqrtf(dg);
    return rs * (1.5f - 0.5f * dg * rs * rs);
}
__device__ __forceinline__ const int* pick_verts(const int* __restrict__ c0,
                                                 const int* __restrict__ c1) {
    bool c0_is_edges = (c0[0] == 0 && c0[1] == 0 && c0[8] == 1 && c0[9] == 1);
    return c0_is_edges ? c1 : c0;
}

// ================= GEMM: Y = X @ W + b via 3xTF32 mma.sync (pre-split operands) ======
__device__ __forceinline__ uint32_t to_tf32(float x) {
    uint32_t r;
    asm("cvt.rna.tf32.f32 %0, %1;" : "=r"(r) : "f"(x));
    return r;
}
__device__ __forceinline__ uint2 split_tf32(float x) {
    uint32_t hi = to_tf32(x);
    uint32_t lo = to_tf32(x - __uint_as_float(hi));
    return make_uint2(hi, lo);
}
__device__ __forceinline__ void mma_tf32(float* c, const uint32_t* a, const uint32_t* b) {
    asm volatile(
        "mma.sync.aligned.m16n8k8.row.col.f32.tf32.tf32.f32 "
        "{%0,%1,%2,%3}, {%4,%5,%6,%7}, {%8,%9}, {%0,%1,%2,%3};"
        : "+f"(c[0]), "+f"(c[1]), "+f"(c[2]), "+f"(c[3])
        : "r"(a[0]), "r"(a[1]), "r"(a[2]), "r"(a[3]), "r"(b[0]), "r"(b[1]));
}

#define CH   64                                 // K-chunk width
#define KK   68                                 // uint2 elems per row (64 + pad)
#define SM_A2 0
#define SM_B2 (128 * KK * 8)                    // 69632
#define SM_GEMM_TOT (2 * 128 * KK * 8)          // 139264 bytes
#define SROW 132                                // epilogue fp32 stage row stride

__global__ void __launch_bounds__(256) k_gemm_tc(const float* __restrict__ X,
                                                 const float* __restrict__ Wm,
                                                 const float* __restrict__ bias) {
    extern __shared__ char smem[];
    uint2* sA2 = (uint2*)(smem + SM_A2);        // [row][kk] (hi,lo), stride KK
    uint2* sB2 = (uint2*)(smem + SM_B2);        // [n][kk]   (hi,lo), stride KK
    const int tid  = threadIdx.x;
    const int wid  = tid >> 5;
    const int lane = tid & 31;
    const int g    = lane >> 2;        // group id 0..7
    const int t    = lane & 3;         // thread-in-group 0..3
    const int row0 = blockIdx.x * 128;
    const int wm   = (wid & 3) * 32;   // warp M offset (0/32/64/96)
    const int wn   = (wid >> 2) * 64;  // warp N offset (0/64)

    float acc[2][8][4];
#pragma unroll
    for (int mt = 0; mt < 2; mt++)
#pragma unroll
        for (int nt = 0; nt < 8; nt++)
#pragma unroll
            for (int j = 0; j < 4; j++) acc[mt][nt][j] = 0.f;

    for (int c = 0; c < 2; c++) {
        // ---- load + split A chunk: X[row0:row0+128, c*64:(c+1)*64] ----
#pragma unroll
        for (int i = 0; i < 8; i++) {
            int idx = tid + i * 256;             // 0..2047 float4s
            int row = idx >> 4, kq = idx & 15;   // 16 float4 per row
            int gr = row0 + row;
            float4 v = make_float4(0.f, 0.f, 0.f, 0.f);
            if (gr < NV) v = *(const float4*)&X[(size_t)gr * D + c * CH + kq * 4];
            uint2 s0 = split_tf32(v.x), s1 = split_tf32(v.y);
            uint2 s2 = split_tf32(v.z), s3 = split_tf32(v.w);
            uint4* dst = (uint4*)&sA2[row * KK + kq * 4];
            dst[0] = make_uint4(s0.x, s0.y, s1.x, s1.y);
            dst[1] = make_uint4(s2.x, s2.y, s3.x, s3.y);
        }
        // ---- load + split B chunk: B[n][kk] = W[c*64+kk][n] ----
#pragma unroll
        for (int i = 0; i < 32; i++) {
            int idx = tid + i * 256;             // 0..8191
            int kk = idx >> 7, n = idx & 127;
            float wv = Wm[(size_t)(c * CH + kk) * D + n];   // coalesced over n
            sB2[n * KK + kk] = split_tf32(wv);
        }
        __syncthreads();

        // ---- compute: 8 k-steps over this chunk ----
#pragma unroll 2
        for (int ks = 0; ks < 8; ks++) {
            const int k0 = ks * 8;
            uint32_t ah[2][4], al[2][4];
#pragma unroll
            for (int mt = 0; mt < 2; mt++) {
                int rb = wm + mt * 16;
                uint2 p0 = sA2[(rb + g) * KK + k0 + t];
                uint2 p1 = sA2[(rb + g + 8) * KK + k0 + t];
                uint2 p2 = sA2[(rb + g) * KK + k0 + t + 4];
                uint2 p3 = sA2[(rb + g + 8) * KK + k0 + t + 4];
                ah[mt][0] = p0.x; al[mt][0] = p0.y;
                ah[mt][1] = p1.x; al[mt][1] = p1.y;
                ah[mt][2] = p2.x; al[mt][2] = p2.y;
                ah[mt][3] = p3.x; al[mt][3] = p3.y;
            }
            uint32_t bh[8][2], bl[8][2];
#pragma unroll
            for (int nt = 0; nt < 8; nt++) {
                int nb = wn + nt * 8 + g;
                uint2 q0 = sB2[nb * KK + k0 + t];
                uint2 q1 = sB2[nb * KK + k0 + t + 4];
                bh[nt][0] = q0.x; bl[nt][0] = q0.y;
                bh[nt][1] = q1.x; bl[nt][1] = q1.y;
            }
#pragma unroll
            for (int mt = 0; mt < 2; mt++)
#pragma unroll
                for (int nt = 0; nt < 8; nt++) {
                    mma_tf32(acc[mt][nt], ah[mt], bh[nt]);
                    mma_tf32(acc[mt][nt], al[mt], bh[nt]);
                    mma_tf32(acc[mt][nt], ah[mt], bl[nt]);
                }
        }
        __syncthreads();
    }

    // ---- stage to smem (reuse sA2 region as fp32), coalesced bias-add writeout ----
    float* stage = (float*)(smem + SM_A2);      // 128 x SROW floats = 67584 B (fits)
#pragma unroll
    for (int mt = 0; mt < 2; mt++)
#pragma unroll
        for (int nt = 0; nt < 8; nt++) {
            int r0 = wm + mt * 16 + g;
            int c0 = wn + nt * 8 + 2 * t;
            *(float2*)&stage[r0 * SROW + c0]       = make_float2(acc[mt][nt][0], acc[mt][nt][1]);
            *(float2*)&stage[(r0 + 8) * SROW + c0] = make_float2(acc[mt][nt][2], acc[mt][nt][3]);
        }
    __syncthreads();
#pragma unroll
    for (int i = 0; i < 16; i++) {
        int idx = tid + i * 256;
        int row = idx >> 5, q = idx & 31;
        int gr = row0 + row;
        if (gr >= NV) continue;
        float4 v = *(const float4*)&stage[row * SROW + q * 4];
        float4 bv = *(const float4*)&bias[q * 4];
        *(float4*)&g_Y[(size_t)gr * D + q * 4] = f4add(v, bv);
    }
}

// ---------------- K2: per-hyperedge argmax pair + degree atomics ----------------
__global__ void __launch_bounds__(256) k_edge(const int* __restrict__ c0,
                                              const int* __restrict__ c1) {
    int w    = (blockIdx.x * blockDim.x + threadIdx.x) >> 5;
    int lane = threadIdx.x & 31;
    if (w >= ME) return;
    const int* verts = pick_verts(c0, c1);

    int4 p0 = ((const int4*)(verts + w * 8))[0];
    int4 p1 = ((const int4*)(verts + w * 8))[1];
    int v[8] = {p0.x, p0.y, p0.z, p0.w, p1.x, p1.y, p1.z, p1.w};

    float4 f[8];
#pragma unroll
    for (int j = 0; j < 8; j++)
        f[j] = *(const float4*)&g_Y[(size_t)v[j] * D + lane * 4];

    float sq[8];
#pragma unroll
    for (int j = 0; j < 8; j++)
        sq[j] = warp_sum(f[j].x * f[j].x + f[j].y * f[j].y +
                         f[j].z * f[j].z + f[j].w * f[j].w);

    float best = -1e30f;
    int bu = 0, bv = 1;
#pragma unroll
    for (int j = 0; j < 8; j++) {
#pragma unroll
        for (int l = j + 1; l < 8; l++) {
            float d = warp_sum(f[j].x * f[l].x + f[j].y * f[l].y +
                               f[j].z * f[l].z + f[j].w * f[l].w);
            float d2 = sq[j] + sq[l] - 2.0f * d;
            if (d2 > best) { best = d2; bu = j; bv = l; }   // first-occurrence, row-major
        }
    }

    int myv = v[0];
#pragma unroll
    for (int j = 1; j < 8; j++) if (lane == j) myv = v[j];
    if (lane < 8) {
        float wd = (lane == bu || lane == bv) ? 7.0f * WMED : 2.0f * WMED;
        atomicAdd(&g_deg[myv], wd);
    }
    if (lane == 0) g_pair[w] = bu | (bv << 4);
}

// ---------------- K3: scatter graph-edge contributions (out starts at 0) ----------------
__global__ void __launch_bounds__(256) k_scatter(float* __restrict__ out,
                                                 const int* __restrict__ c0,
                                                 const int* __restrict__ c1) {
    int w    = (blockIdx.x * blockDim.x + threadIdx.x) >> 5;
    int lane = threadIdx.x & 31;
    if (w >= ME) return;
    const int* verts = pick_verts(c0, c1);

    int4 p0 = ((const int4*)(verts + w * 8))[0];
    int4 p1 = ((const int4*)(verts + w * 8))[1];
    int v[8] = {p0.x, p0.y, p0.z, p0.w, p1.x, p1.y, p1.z, p1.w};

    int myv = v[0];
#pragma unroll
    for (int j = 1; j < 8; j++) if (lane == j) myv = v[j];
    float mydinv = 0.f;
    if (lane < 8) mydinv = rsqrt_ref(1.0f + g_deg[myv]);
    float dv[8];
#pragma unroll
    for (int j = 0; j < 8; j++) dv[j] = __shfl_sync(0xffffffffu, mydinv, j);

    int code = g_pair[w];
    int bu = code & 15, bv = code >> 4;

    float4 su = make_float4(0.f, 0.f, 0.f, 0.f);
    float4 sv = su;
    float4 smed = su;
#pragma unroll
    for (int j = 0; j < 8; j++) {
        float4 f = *(const float4*)&g_Y[(size_t)v[j] * D + lane * 4];
        f = f4scale(f, dv[j]);                      // Xs row
        if (j == bu)      su = f;
        else if (j == bv) sv = f;
        else              smed = f4add(smed, f);
    }

    float4 Au = f4scale(f4add(sv, smed), WMED);
    float4 Av = f4scale(f4add(su, smed), WMED);
    float4 Am = f4scale(f4add(su, sv),   WMED);

#pragma unroll
    for (int j = 0; j < 8; j++) {
        float4 val = (j == bu) ? Au : ((j == bv) ? Av : Am);
        red_add_v4(&out[(size_t)v[j] * D + lane * 4], val);
    }
}

// ---------------- K4: out = relu((out + Y*dinv) * dinv) ----------------
__global__ void k_final(float* __restrict__ out) {
    int i = blockIdx.x * blockDim.x + threadIdx.x;
    if (i >= NV * (D / 4)) return;
    int row = i >> 5;
    float r = rsqrt_ref(1.0f + g_deg[row]);
    float4 o = ((float4*)out)[i];
    float4 y = ((const float4*)g_Y)[i];
    o.x = fmaxf((o.x + y.x * r) * r, 0.f);
    o.y = fmaxf((o.y + y.y * r) * r, 0.f);
    o.z = fmaxf((o.z + y.z * r) * r, 0.f);
    o.w = fmaxf((o.w + y.w * r) * r, 0.f);
    ((float4*)out)[i] = o;
}

// ---------------- launcher ----------------
extern "C" void kernel_launch(void* const* d_in, const int* in_sizes, int n_in,
                              void* d_out, int out_size) {
    const float* X = nullptr;
    const float* W = nullptr;
    const float* b = nullptr;
    const int* c0 = nullptr;
    const int* c1 = nullptr;

    for (int i = 0; i < n_in; i++) {
        int s = in_sizes[i];
        if (s == NV * D)        X = (const float*)d_in[i];
        else if (s == D * D)    W = (const float*)d_in[i];
        else if (s == D)        b = (const float*)d_in[i];
        else if (s == ME * 8) { if (!c0) c0 = (const int*)d_in[i]; else c1 = (const int*)d_in[i]; }
    }
    float* out = (float*)d_out;

    void* degPtr = nullptr;
    cudaGetSymbolAddress(&degPtr, g_deg);
    cudaFuncSetAttribute(k_gemm_tc, cudaFuncAttributeMaxDynamicSharedMemorySize, SM_GEMM_TOT);

    cudaMemsetAsync(degPtr, 0, (size_t)NV * sizeof(float), 0);
    cudaMemsetAsync(out, 0, (size_t)NV * D * sizeof(float), 0);
    k_gemm_tc<<<(NV + 127) / 128, 256, SM_GEMM_TOT>>>(X, W, b);
    k_edge<<<(ME * 32 + 255) / 256, 256>>>(c0, c1);
    k_scatter<<<(ME * 32 + 255) / 256, 256>>>(out, c0, c1);
    k_final<<<(NV * (D / 4) + 255) / 256, 256>>>(out);
}

// round 7
// speedup vs baseline: 1.0539x; 1.0539x over previous
#include <cuda_runtime.h>
#include <cstdint>

#define NV 100000
#define ME 50000
#define D  128
#define WMED (1.0f / 13.0f)

// ---------------- scratch (device globals; no runtime allocation) ----------------
__device__ float g_Y[(size_t)NV * D];   // Y (pre-scaled linear output)
__device__ float g_deg[NV];             // extra degree (actual deg = 1 + g_deg); memset 0
__device__ int   g_pair[ME];

// ---------------- helpers ----------------
__device__ __forceinline__ float4 f4add(float4 a, float4 b) {
    return make_float4(a.x + b.x, a.y + b.y, a.z + b.z, a.w + b.w);
}
__device__ __forceinline__ float4 f4scale(float4 a, float s) {
    return make_float4(a.x * s, a.y * s, a.z * s, a.w * s);
}
__device__ __forceinline__ void red_add_v4(float* p, float4 v) {
    asm volatile("red.global.add.v4.f32 [%0], {%1,%2,%3,%4};"
                 :: "l"(p), "f"(v.x), "f"(v.y), "f"(v.z), "f"(v.w) : "memory");
}
__device__ __forceinline__ float warp_sum(float v) {
#pragma unroll
    for (int o = 16; o > 0; o >>= 1) v += __shfl_xor_sync(0xffffffffu, v, o);
    return v;
}
__device__ __forceinline__ float rsqrt_ref(float dg) {
    float rs = rsqrtf(dg);
    return rs * (1.5f - 0.5f * dg * rs * rs);
}
__device__ __forceinline__ const int* pick_verts(const int* __restrict__ c0,
                                                 const int* __restrict__ c1) {
    bool c0_is_edges = (c0[0] == 0 && c0[1] == 0 && c0[8] == 1 && c0[9] == 1);
    return c0_is_edges ? c1 : c0;
}
__device__ __forceinline__ unsigned long long pack2(float a) {
    unsigned long long r;
    asm("mov.b64 %0, {%1, %1};" : "=l"(r) : "f"(a));
    return r;
}
__device__ __forceinline__ void fma2(unsigned long long& acc, unsigned long long a,
                                     unsigned long long b) {
    asm("fma.rn.f32x2 %0, %1, %2, %0;" : "+l"(acc) : "l"(a), "l"(b));
}
__device__ __forceinline__ void unpack2(unsigned long long p, float& lo, float& hi) {
    asm("mov.b64 {%0, %1}, %2;" : "=f"(lo), "=f"(hi) : "l"(p));
}
__device__ __forceinline__ void cp_async16(void* dst_smem, const void* src_gmem) {
    uint32_t d = (uint32_t)__cvta_generic_to_shared(dst_smem);
    asm volatile("cp.async.ca.shared.global [%0], [%1], 16;" :: "r"(d), "l"(src_gmem));
}

// ---------------- dummy kernels (position k_gemm as the 4th launch for ncu) ------
__global__ void k_nop1() {}
__global__ void k_nop2() {}
__global__ void k_nop3() {}

// ================= K1: Y = X @ W + b (fp32 FFMA2, whole-K, single sync) =========
// BM=128, BN=128, K=128 all staged; 256 threads, 8x8 per-thread register tile.
#define GROW 132
#define SM_GEMM_TOT (2 * 128 * GROW * 4)        // 135168 bytes

__global__ void __launch_bounds__(256) k_gemm(const float* __restrict__ X,
                                              const float* __restrict__ Wm,
                                              const float* __restrict__ bias) {
    extern __shared__ float smem[];
    float* sA = smem;                   // [k][row], stride GROW
    float* sB = smem + 128 * GROW;      // [k][col], stride GROW
    const int tid  = threadIdx.x;
    const int row0 = blockIdx.x * 128;
    const int tx   = tid & 15;          // col group
    const int ty   = tid >> 4;          // row group

    // ---- B = W straight copy via cp.async (L2-resident after first wave) ----
#pragma unroll
    for (int i = 0; i < 16; i++) {
        int idx = tid + i * 256;        // 0..4095 float4s
        int k = idx >> 5, c4 = idx & 31;
        cp_async16(&sB[k * GROW + c4 * 4], &Wm[(size_t)k * D + c4 * 4]);
    }
    asm volatile("cp.async.commit_group;" ::: "memory");

    // ---- A transpose-stage (coalesced global float4, scattered STS.32) ----
#pragma unroll
    for (int i = 0; i < 16; i++) {
        int k0  = (i >> 2) * 32;              // 32-k chunk
        int sub = tid + (i & 3) * 256;        // 0..1023
        int r   = sub >> 3;                   // 0..127 row
        int kq  = sub & 7;                    // float4 along k
        int gr  = row0 + r;
        float4 xv = make_float4(0.f, 0.f, 0.f, 0.f);
        if (gr < NV) xv = *(const float4*)&X[(size_t)gr * D + k0 + kq * 4];
        sA[(k0 + kq * 4 + 0) * GROW + r] = xv.x;
        sA[(k0 + kq * 4 + 1) * GROW + r] = xv.y;
        sA[(k0 + kq * 4 + 2) * GROW + r] = xv.z;
        sA[(k0 + kq * 4 + 3) * GROW + r] = xv.w;
    }
    asm volatile("cp.async.wait_group 0;" ::: "memory");
    __syncthreads();

    // ---- compute: uninterrupted 128-deep k loop ----
    unsigned long long acc2[8][4];
#pragma unroll
    for (int r = 0; r < 8; r++)
#pragma unroll
        for (int c = 0; c < 4; c++) acc2[r][c] = 0ull;

#pragma unroll 8
    for (int k = 0; k < 128; k++) {
        float4 a0 = *(const float4*)&sA[k * GROW + ty * 4];
        float4 a1 = *(const float4*)&sA[k * GROW + 64 + ty * 4];
        ulonglong2 bq0 = *(const ulonglong2*)&sB[k * GROW + tx * 4];
        ulonglong2 bq1 = *(const ulonglong2*)&sB[k * GROW + 64 + tx * 4];
        unsigned long long b2[4] = {bq0.x, bq0.y, bq1.x, bq1.y};
        float a[8] = {a0.x, a0.y, a0.z, a0.w, a1.x, a1.y, a1.z, a1.w};
#pragma unroll
        for (int r = 0; r < 8; r++) {
            unsigned long long aa = pack2(a[r]);
#pragma unroll
            for (int c = 0; c < 4; c++) fma2(acc2[r][c], aa, b2[c]);
        }
    }

    // ---- epilogue: direct global writes with bias ----
    float4 bv0 = *(const float4*)&bias[tx * 4];
    float4 bv1 = *(const float4*)&bias[64 + tx * 4];
#pragma unroll
    for (int r = 0; r < 8; r++) {
        int lr = (r < 4) ? (ty * 4 + r) : (64 + ty * 4 + (r - 4));
        int gr = row0 + lr;
        if (gr >= NV) continue;
        float o[8];
#pragma unroll
        for (int c = 0; c < 4; c++) unpack2(acc2[r][c], o[2 * c], o[2 * c + 1]);
        float4 o0 = make_float4(o[0] + bv0.x, o[1] + bv0.y, o[2] + bv0.z, o[3] + bv0.w);
        float4 o1 = make_float4(o[4] + bv1.x, o[5] + bv1.y, o[6] + bv1.z, o[7] + bv1.w);
        *(float4*)&g_Y[(size_t)gr * D + tx * 4]      = o0;
        *(float4*)&g_Y[(size_t)gr * D + 64 + tx * 4] = o1;
    }
}

// ---------------- K2: per-hyperedge argmax pair + degree atomics ----------------
__global__ void __launch_bounds__(256) k_edge(const int* __restrict__ c0,
                                              const int* __restrict__ c1) {
    int w    = (blockIdx.x * blockDim.x + threadIdx.x) >> 5;
    int lane = threadIdx.x & 31;
    if (w >= ME) return;
    const int* verts = pick_verts(c0, c1);

    int4 p0 = ((const int4*)(verts + w * 8))[0];
    int4 p1 = ((const int4*)(verts + w * 8))[1];
    int v[8] = {p0.x, p0.y, p0.z, p0.w, p1.x, p1.y, p1.z, p1.w};

    float4 f[8];
#pragma unroll
    for (int j = 0; j < 8; j++)
        f[j] = *(const float4*)&g_Y[(size_t)v[j] * D + lane * 4];

    float sq[8];
#pragma unroll
    for (int j = 0; j < 8; j++)
        sq[j] = warp_sum(f[j].x * f[j].x + f[j].y * f[j].y +
                         f[j].z * f[j].z + f[j].w * f[j].w);

    float best = -1e30f;
    int bu = 0, bv = 1;
#pragma unroll
    for (int j = 0; j < 8; j++) {
#pragma unroll
        for (int l = j + 1; l < 8; l++) {
            float d = warp_sum(f[j].x * f[l].x + f[j].y * f[l].y +
                               f[j].z * f[l].z + f[j].w * f[l].w);
            float d2 = sq[j] + sq[l] - 2.0f * d;
            if (d2 > best) { best = d2; bu = j; bv = l; }   // first-occurrence, row-major
        }
    }

    int myv = v[0];
#pragma unroll
    for (int j = 1; j < 8; j++) if (lane == j) myv = v[j];
    if (lane < 8) {
        float wd = (lane == bu || lane == bv) ? 7.0f * WMED : 2.0f * WMED;
        atomicAdd(&g_deg[myv], wd);
    }
    if (lane == 0) g_pair[w] = bu | (bv << 4);
}

// ---------------- K3: scatter graph-edge contributions (out starts at 0) ----------------
__global__ void __launch_bounds__(256) k_scatter(float* __restrict__ out,
                                                 const int* __restrict__ c0,
                                                 const int* __restrict__ c1) {
    int w    = (blockIdx.x * blockDim.x + threadIdx.x) >> 5;
    int lane = threadIdx.x & 31;
    if (w >= ME) return;
    const int* verts = pick_verts(c0, c1);

    int4 p0 = ((const int4*)(verts + w * 8))[0];
    int4 p1 = ((const int4*)(verts + w * 8))[1];
    int v[8] = {p0.x, p0.y, p0.z, p0.w, p1.x, p1.y, p1.z, p1.w};

    int myv = v[0];
#pragma unroll
    for (int j = 1; j < 8; j++) if (lane == j) myv = v[j];
    float mydinv = 0.f;
    if (lane < 8) mydinv = rsqrt_ref(1.0f + g_deg[myv]);
    float dv[8];
#pragma unroll
    for (int j = 0; j < 8; j++) dv[j] = __shfl_sync(0xffffffffu, mydinv, j);

    int code = g_pair[w];
    int bu = code & 15, bv = code >> 4;

    float4 su = make_float4(0.f, 0.f, 0.f, 0.f);
    float4 sv = su;
    float4 smed = su;
#pragma unroll
    for (int j = 0; j < 8; j++) {
        float4 f = *(const float4*)&g_Y[(size_t)v[j] * D + lane * 4];
        f = f4scale(f, dv[j]);                      // Xs row
        if (j == bu)      su = f;
        else if (j == bv) sv = f;
        else              smed = f4add(smed, f);
    }

    float4 Au = f4scale(f4add(sv, smed), WMED);
    float4 Av = f4scale(f4add(su, smed), WMED);
    float4 Am = f4scale(f4add(su, sv),   WMED);

#pragma unroll
    for (int j = 0; j < 8; j++) {
        float4 val = (j == bu) ? Au : ((j == bv) ? Av : Am);
        red_add_v4(&out[(size_t)v[j] * D + lane * 4], val);
    }
}

// ---------------- K4: out = relu((out + Y*dinv) * dinv) ----------------
__global__ void k_final(float* __restrict__ out) {
    int i = blockIdx.x * blockDim.x + threadIdx.x;
    if (i >= NV * (D / 4)) return;
    int row = i >> 5;
    float r = rsqrt_ref(1.0f + g_deg[row]);
    float4 o = ((float4*)out)[i];
    float4 y = ((const float4*)g_Y)[i];
    o.x = fmaxf((o.x + y.x * r) * r, 0.f);
    o.y = fmaxf((o.y + y.y * r) * r, 0.f);
    o.z = fmaxf((o.z + y.z * r) * r, 0.f);
    o.w = fmaxf((o.w + y.w * r) * r, 0.f);
    ((float4*)out)[i] = o;
}

// ---------------- launcher ----------------
extern "C" void kernel_launch(void* const* d_in, const int* in_sizes, int n_in,
                              void* d_out, int out_size) {
    const float* X = nullptr;
    const float* W = nullptr;
    const float* b = nullptr;
    const int* c0 = nullptr;
    const int* c1 = nullptr;

    for (int i = 0; i < n_in; i++) {
        int s = in_sizes[i];
        if (s == NV * D)        X = (const float*)d_in[i];
        else if (s == D * D)    W = (const float*)d_in[i];
        else if (s == D)        b = (const float*)d_in[i];
        else if (s == ME * 8) { if (!c0) c0 = (const int*)d_in[i]; else c1 = (const int*)d_in[i]; }
    }
    float* out = (float*)d_out;

    void* degPtr = nullptr;
    cudaGetSymbolAddress(&degPtr, g_deg);
    cudaFuncSetAttribute(k_gemm, cudaFuncAttributeMaxDynamicSharedMemorySize, SM_GEMM_TOT);

    cudaMemsetAsync(degPtr, 0, (size_t)NV * sizeof(float), 0);
    cudaMemsetAsync(out, 0, (size_t)NV * D * sizeof(float), 0);
    k_nop1<<<1, 32>>>();
    k_nop2<<<1, 32>>>();
    k_nop3<<<1, 32>>>();
    k_gemm<<<(NV + 127) / 128, 256, SM_GEMM_TOT>>>(X, W, b);     // 4th launch -> ncu
    k_edge<<<(ME * 32 + 255) / 256, 256>>>(c0, c1);
    k_scatter<<<(ME * 32 + 255) / 256, 256>>>(out, c0, c1);
    k_final<<<(NV * (D / 4) + 255) / 256, 256>>>(out);
}